// round 14
// baseline (speedup 1.0000x reference)
#include <cuda_runtime.h>
#include <math.h>
#include <stdint.h>

// Problem constants
#define BB    16
#define CC    64
#define HWSZ  4096
#define NPIX  65536
#define KK    1024
#define DD    64
#define NEL   4194304
#define TILE_P 64
#define CHUNK  128
#define NTILE  1024            // NPIX / TILE_P

// Device scratch
__device__ float g_counts[KK];
__device__ float g_cnorm[KK];
__device__ float g_part[NTILE];
__device__ int   g_done;

// ---------------------------------------------------------------------------
// Kernel 1: codebook norms (reference rounding) + zero histogram + reset flag.
// ---------------------------------------------------------------------------
extern __shared__ float psm[];

__global__ void prep_kernel(const float* __restrict__ cb) {
    const int tid  = threadIdx.x;
    const int base = blockIdx.x * 64;            // 64 codes per block

    for (int i = tid; i < 64 * DD; i += 256) {
        int k = i >> 6, d = i & 63;
        psm[k * 65 + d] = cb[(size_t)(base + k) * DD + d];
    }
    __syncthreads();

    if (tid < 64) {
        float s = 0.f;
        #pragma unroll
        for (int d = 0; d < DD; d++) {
            float v = psm[tid * 65 + d];
            s = __fadd_rn(s, __fmul_rn(v, v));   // reference-exact cn
        }
        g_cnorm[base + tid]  = s;
        g_counts[base + tid] = 0.f;
    }
    if (blockIdx.x == 0 && tid == 0) g_done = 0;
}

// ---------------------------------------------------------------------------
// Kernel 2: fused exact argmin (fp32 FFMA GEMM) + gather + quantized store +
//           loss partial + last-block finalize.
// 1024 blocks x 128 threads; block = 64 pixels (4 blocks/SM resident, fixes
// wave quantization); thread (tx,ty): pixels tx*8..+7, codes ty*8..+7/chunk.
// smem (floats): xs[4096] | cs[8448] | cns[128] | nss[64] | sidx[64] = 12800
// ---------------------------------------------------------------------------
extern __shared__ float smem[];

__global__ void __launch_bounds__(128, 4)
argmin_fused_kernel(const float* __restrict__ in, const float* __restrict__ cb,
                    float* __restrict__ outq,
                    const float* __restrict__ beta,
                    float* __restrict__ loss_out, float* __restrict__ pp_out) {
    float* xs   = smem;                       // 4096 floats (64d x 64p)
    float* cs   = smem + 4096;                // 8448 floats (64 x 132)
    float* cns  = smem + 12544;               // 128
    float* nss  = smem + 12672;               // 64
    int*   sidx = (int*)(smem + 12736);       // 64   (total 12800 words = 51200B)

    const int tid = threadIdx.x;
    const int tx  = tid & 7;    // pixel group: pixels tx*8 .. +7
    const int ty  = tid >> 3;   // code group:  codes  ty*8 .. +7 (in chunk)

    const int n0  = blockIdx.x * TILE_P;      // 64 | 4096: never crosses batch
    const int b   = n0 >> 12;
    const int hw0 = n0 & 4095;
    const float* xin = in + (size_t)b * CC * HWSZ + hw0;

    // load x tile: xs[d][p] (coalesced 256B rows)
    for (int i = tid; i < DD * TILE_P; i += 128) {
        int d = i >> 6, p = i & 63;
        xs[d * 64 + p] = xin[(size_t)d * HWSZ + p];
    }
    __syncthreads();

    // exact ||x||^2 (reference rounding)
    if (tid < 64) {
        float s = 0.f;
        #pragma unroll
        for (int d = 0; d < DD; d++) {
            float v = xs[d * 64 + tid];
            s = __fadd_rn(s, __fmul_rn(v, v));
        }
        nss[tid] = s;
    }

    float bd[8];
    int   bi[8];
    #pragma unroll
    for (int i = 0; i < 8; i++) { bd[i] = 3.4e38f; bi[i] = 0; }

    for (int kc = 0; kc < KK; kc += CHUNK) {
        __syncthreads();
        // load codebook chunk transposed: cs[d][k] = cb[kc+k][d]
        for (int i = tid; i < CHUNK * 64; i += 128) {
            int k = i >> 6, d = i & 63;
            cs[d * 132 + k] = cb[(size_t)(kc + k) * DD + d];
        }
        cns[tid] = g_cnorm[kc + tid];
        __syncthreads();

        float acc[8][8];
        #pragma unroll
        for (int i = 0; i < 8; i++)
            #pragma unroll
            for (int j = 0; j < 8; j++) acc[i][j] = 0.f;

        // dot: strictly d-ascending single-accumulator fp32 FMA chains
        #pragma unroll 2
        for (int d = 0; d < 64; d++) {
            const float4 xa  = *reinterpret_cast<const float4*>(&xs[d * 64 + tx * 8]);
            const float4 xb2 = *reinterpret_cast<const float4*>(&xs[d * 64 + tx * 8 + 4]);
            const float4 ca  = *reinterpret_cast<const float4*>(&cs[d * 132 + ty * 8]);
            const float4 cb2 = *reinterpret_cast<const float4*>(&cs[d * 132 + ty * 8 + 4]);
            float xv[8] = {xa.x, xa.y, xa.z, xa.w, xb2.x, xb2.y, xb2.z, xb2.w};
            float cv[8] = {ca.x, ca.y, ca.z, ca.w, cb2.x, cb2.y, cb2.z, cb2.w};
            #pragma unroll
            for (int i = 0; i < 8; i++)
                #pragma unroll
                for (int j = 0; j < 8; j++)
                    acc[i][j] = __fmaf_rn(xv[i], cv[j], acc[i][j]);
        }

        // score fl(fl(ns+cn) - fl(2*dot)) == fmaf(-2,dot,fl(ns+cn)) (2*dot exact)
        // ascending k + strict '<' keeps first-index min within this thread.
        #pragma unroll
        for (int i = 0; i < 8; i++) {
            float ns = nss[tx * 8 + i];
            #pragma unroll
            for (int j = 0; j < 8; j++) {
                float s = __fmaf_rn(-2.0f, acc[i][j], __fadd_rn(ns, cns[ty * 8 + j]));
                if (s < bd[i]) { bd[i] = s; bi[i] = kc + ty * 8 + j; }
            }
        }
    }

    // cross-thread (over 16 ty groups) min reduction in cs region (xs intact)
    __syncthreads();
    float* rd = cs;                            // [16][64]
    int*   ri = (int*)(cs + 1024);             // [16][64]
    #pragma unroll
    for (int i = 0; i < 8; i++) {
        rd[ty * 64 + tx * 8 + i] = bd[i];
        ri[ty * 64 + tx * 8 + i] = bi[i];
    }
    __syncthreads();
    if (tid < 64) {
        float best = rd[tid];
        int   bidx = ri[tid];
        // explicit first-index tiebreak
        #pragma unroll
        for (int t = 1; t < 16; t++) {
            float v  = rd[t * 64 + tid];
            int   vi = ri[t * 64 + tid];
            if (v < best || (v == best && vi < bidx)) { best = v; bidx = vi; }
        }
        sidx[tid] = bidx;
        atomicAdd(&g_counts[bidx], 1.0f);      // integer-valued: deterministic
    }
    __syncthreads();

    // fused gather + quantized output + loss partial (xs still valid).
    // thread t: pixel p = t&63 (coalesced), channels (t>>6)*32 + ii.
    // outq = out+1 is 4-mod-16 aligned -> scalar stores (required).
    {
        const int p   = tid & 63;
        const int c0  = (tid >> 6) * 32;
        const int idx = sidx[p];
        const float* crow = cb + (size_t)idx * DD;
        float* obase = outq + (size_t)b * CC * HWSZ + hw0 + p;
        float part = 0.f;
        #pragma unroll
        for (int ii = 0; ii < 32; ii++) {
            int c = c0 + ii;
            float x  = xs[c * 64 + p];
            float q  = __ldg(&crow[c]);
            float dv = q - x;
            obase[(size_t)c * HWSZ] = x + dv;
            part = __fmaf_rn(dv, dv, part);
        }
        // deterministic block reduction
        #pragma unroll
        for (int o = 16; o; o >>= 1)
            part += __shfl_xor_sync(0xffffffffu, part, o);
        __shared__ float ws[4];
        if ((tid & 31) == 0) ws[tid >> 5] = part;
        __syncthreads();
        if (tid == 0)
            g_part[blockIdx.x] = (ws[0] + ws[1]) + (ws[2] + ws[3]);
    }

    // ---- last-block finalize (threadfence reduction pattern) ----
    __shared__ int is_last;
    if (tid == 0) {
        __threadfence();
        int v = atomicAdd(&g_done, 1);
        is_last = (v == NTILE - 1) ? 1 : 0;
    }
    __syncthreads();
    if (is_last) {
        __threadfence();   // all blocks' g_part/g_counts visible

        float ls = 0.f;
        #pragma unroll
        for (int i = 0; i < 8; i++) ls += g_part[tid * 8 + i];

        float ent = 0.f;
        #pragma unroll
        for (int i = 0; i < 8; i++) {
            float em = g_counts[tid * 8 + i] * (1.0f / (float)NPIX);
            ent += em * logf(em + 1e-10f);
        }

        #pragma unroll
        for (int o = 16; o; o >>= 1) {
            ls  += __shfl_xor_sync(0xffffffffu, ls, o);
            ent += __shfl_xor_sync(0xffffffffu, ent, o);
        }
        __shared__ float wl[4], we[4];
        if ((tid & 31) == 0) { wl[tid >> 5] = ls; we[tid >> 5] = ent; }
        __syncthreads();
        if (tid == 0) {
            float tl = (wl[0] + wl[1]) + (wl[2] + wl[3]);
            float te = (we[0] + we[1]) + (we[2] + we[3]);
            float mean = tl / (float)NEL;
            *loss_out = (1.0f + *beta) * 10.0f * mean;   // KLD_SCALE = 10
            *pp_out   = expf(-te);
        }
    }
}

// ---------------------------------------------------------------------------
// Launch
// ---------------------------------------------------------------------------
extern "C" void kernel_launch(void* const* d_in, const int* in_sizes, int n_in,
                              void* d_out, int out_size) {
    const float* in   = nullptr;
    const float* cb   = nullptr;
    const float* beta = nullptr;
    for (int i = 0; i < n_in; i++) {
        if      (in_sizes[i] == NEL)     in   = (const float*)d_in[i];
        else if (in_sizes[i] == KK * DD) cb   = (const float*)d_in[i];
        else if (in_sizes[i] == 1)       beta = (const float*)d_in[i];
    }

    float* out      = (float*)d_out;
    float* loss_out = out;
    float* q_out    = out + 1;
    float* pp_out   = out + (out_size - 1);

    const int prep_smem = 64 * 65 * 4;           // 16640 B
    const int main_smem = 12800 * 4;             // 51200 B (4 blocks/SM)
    cudaFuncSetAttribute(argmin_fused_kernel,
                         cudaFuncAttributeMaxDynamicSharedMemorySize, main_smem);

    prep_kernel<<<16, 256, prep_smem>>>(cb);
    argmin_fused_kernel<<<NTILE, 128, main_smem>>>(in, cb, q_out,
                                                   beta, loss_out, pp_out);
}

// round 15
// speedup vs baseline: 1.1364x; 1.1364x over previous
#include <cuda_runtime.h>
#include <math.h>
#include <stdint.h>

// Problem constants
#define BB    16
#define CC    64
#define HWSZ  4096
#define NPIX  65536
#define KK    1024
#define DD    64
#define NEL   4194304
#define TILE_P 128
#define CHUNK  128
#define NTILE  512             // NPIX / TILE_P

// Device scratch
__device__ float g_counts[KK];
__device__ float g_cnorm[KK];
__device__ float g_part[NTILE];
__device__ __align__(16) float g_ct[DD * KK];   // transposed codebook [d][k]
__device__ int   g_done;

// ---------------------------------------------------------------------------
// Kernel 1: cnorm (reference rounding) + transposed codebook + zero hist.
// 16 blocks x 256 threads, 64 codes per block; smem-staged for coalescing.
// ---------------------------------------------------------------------------
extern __shared__ float psm[];

__global__ void prep_kernel(const float* __restrict__ cb) {
    const int tid  = threadIdx.x;
    const int base = blockIdx.x * 64;            // 64 codes per block

    // coalesced load: psm[k][65] rows
    for (int i = tid; i < 64 * DD; i += 256) {
        int k = i >> 6, d = i & 63;
        psm[k * 65 + d] = cb[(size_t)(base + k) * DD + d];
    }
    __syncthreads();

    if (tid < 64) {
        float s = 0.f;
        #pragma unroll
        for (int d = 0; d < DD; d++) {
            float v = psm[tid * 65 + d];
            s = __fadd_rn(s, __fmul_rn(v, v));   // reference-exact cn
        }
        g_cnorm[base + tid]  = s;
        g_counts[base + tid] = 0.f;
    }
    // transposed writes: consecutive tid -> consecutive k (coalesced 256B);
    // smem reads stride-65 -> conflict-free
    for (int i = tid; i < 64 * DD; i += 256) {
        int d = i >> 6, k = i & 63;
        g_ct[d * KK + base + k] = psm[k * 65 + d];
    }
    if (blockIdx.x == 0 && tid == 0) g_done = 0;
}

// ---------------------------------------------------------------------------
// cp.async 16B copy of one 128-code chunk (transposed source is contiguous)
// dst rows padded to 132 floats (528B, 16B-aligned).
// ---------------------------------------------------------------------------
__device__ __forceinline__ void issue_chunk_copy(uint32_t cs_addr,
                                                 const float* __restrict__ gsrc,
                                                 int tid) {
    #pragma unroll
    for (int r = 0; r < 8; r++) {
        int i  = tid + r * 256;          // < 2048
        int d  = i >> 5, k4 = i & 31;
        uint32_t dst = cs_addr + (uint32_t)(d * 528 + k4 * 16);
        const float* src = gsrc + d * KK + k4 * 4;
        asm volatile("cp.async.cg.shared.global [%0], [%1], 16;"
                     :: "r"(dst), "l"(src));
    }
}

// ---------------------------------------------------------------------------
// Kernel 2: fused exact argmin (fp32 FFMA GEMM, double-buffered cp.async) +
//           gather + quantized store + loss partial + last-block finalize.
// 512 blocks x 256 threads; block = 128 pixels; thread (tx,ty) owns
// pixels tx*8..+7 and codes ty*8..+7 within each 128-code chunk.
// smem (floats): xs[8192] | cs0[8448] | cs1[8448] | cns[1024] | nss[128] | sidx[128]
// ---------------------------------------------------------------------------
extern __shared__ float smem[];

__global__ void __launch_bounds__(256, 2)
argmin_fused_kernel(const float* __restrict__ in, const float* __restrict__ cb,
                    float* __restrict__ outq,
                    const float* __restrict__ beta,
                    float* __restrict__ loss_out, float* __restrict__ pp_out) {
    float* xs   = smem;                        // 8192
    float* cs0  = smem + 8192;                 // 8448 (64 x 132)
    float* cs1  = smem + 16640;                // 8448
    float* cns  = smem + 25088;                // 1024
    float* nss  = smem + 26112;                // 128
    int*   sidx = (int*)(smem + 26240);        // 128  (total 26368 = 105472B)

    const int tid = threadIdx.x;
    const int tx  = tid & 15;   // pixel group: pixels tx*8 .. +7
    const int ty  = tid >> 4;   // code group:  codes  ty*8 .. +7 (in chunk)

    const uint32_t cs0_a = (uint32_t)__cvta_generic_to_shared(cs0);
    const uint32_t cs1_a = (uint32_t)__cvta_generic_to_shared(cs1);

    const int n0  = blockIdx.x * TILE_P;       // never crosses batch boundary
    const int b   = n0 >> 12;
    const int hw0 = n0 & 4095;
    const float* xin = in + (size_t)b * CC * HWSZ + hw0;

    // prologue: kick off chunk 0 copy before anything else
    issue_chunk_copy(cs0_a, g_ct, tid);
    asm volatile("cp.async.commit_group;" ::: "memory");

    // load x tile: xs[d][p] (coalesced) + all cnorms
    for (int i = tid; i < 64 * 128; i += 256) {
        int d = i >> 7, p = i & 127;
        xs[d * 128 + p] = xin[(size_t)d * HWSZ + p];
    }
    for (int i = tid; i < KK; i += 256) cns[i] = g_cnorm[i];
    __syncthreads();

    // exact ||x||^2 (reference rounding)
    if (tid < 128) {
        float s = 0.f;
        #pragma unroll
        for (int d = 0; d < DD; d++) {
            float v = xs[d * 128 + tid];
            s = __fadd_rn(s, __fmul_rn(v, v));
        }
        nss[tid] = s;
    }

    float bd[8];
    int   bi[8];
    #pragma unroll
    for (int i = 0; i < 8; i++) { bd[i] = 3.4e38f; bi[i] = 0; }

    #pragma unroll 1
    for (int ch = 0; ch < 8; ch++) {
        // issue next chunk copy into the other buffer (safe: that buffer was
        // last read in iteration ch-1, protected by trailing __syncthreads)
        if (ch < 7) {
            issue_chunk_copy((ch & 1) ? cs0_a : cs1_a,
                             g_ct + (ch + 1) * CHUNK, tid);
            asm volatile("cp.async.commit_group;" ::: "memory");
            asm volatile("cp.async.wait_group 1;" ::: "memory");
        } else {
            asm volatile("cp.async.wait_group 0;" ::: "memory");
        }
        __syncthreads();

        const float* cs  = (ch & 1) ? cs1 : cs0;
        const float* cnc = cns + ch * CHUNK;

        float acc[8][8];
        #pragma unroll
        for (int i = 0; i < 8; i++)
            #pragma unroll
            for (int j = 0; j < 8; j++) acc[i][j] = 0.f;

        // dot: strictly d-ascending single-accumulator fp32 FMA chains
        #pragma unroll 2
        for (int d = 0; d < 64; d++) {
            const float4 xa  = *reinterpret_cast<const float4*>(&xs[d * 128 + tx * 8]);
            const float4 xb2 = *reinterpret_cast<const float4*>(&xs[d * 128 + tx * 8 + 4]);
            const float4 ca  = *reinterpret_cast<const float4*>(&cs[d * 132 + ty * 8]);
            const float4 cb2 = *reinterpret_cast<const float4*>(&cs[d * 132 + ty * 8 + 4]);
            float xv[8] = {xa.x, xa.y, xa.z, xa.w, xb2.x, xb2.y, xb2.z, xb2.w};
            float cv[8] = {ca.x, ca.y, ca.z, ca.w, cb2.x, cb2.y, cb2.z, cb2.w};
            #pragma unroll
            for (int i = 0; i < 8; i++)
                #pragma unroll
                for (int j = 0; j < 8; j++)
                    acc[i][j] = __fmaf_rn(xv[i], cv[j], acc[i][j]);
        }

        // score fl(fl(ns+cn) - fl(2*dot)) == fmaf(-2,dot,fl(ns+cn)) (2*dot exact)
        // ascending k + strict '<' keeps first-index min within this thread.
        const int kc = ch * CHUNK;
        #pragma unroll
        for (int i = 0; i < 8; i++) {
            float ns = nss[tx * 8 + i];
            #pragma unroll
            for (int j = 0; j < 8; j++) {
                float s = __fmaf_rn(-2.0f, acc[i][j], __fadd_rn(ns, cnc[ty * 8 + j]));
                if (s < bd[i]) { bd[i] = s; bi[i] = kc + ty * 8 + j; }
            }
        }
        __syncthreads();   // all reads of cs done before its refill (ch+2 issue)
    }

    // cross-thread (over ty) min reduction in cs0 region (xs preserved!)
    float* rd = cs0;                           // [16][128]
    int*   ri = (int*)(cs0 + 2048);            // [16][128]
    #pragma unroll
    for (int i = 0; i < 8; i++) {
        rd[ty * 128 + tx * 8 + i] = bd[i];
        ri[ty * 128 + tx * 8 + i] = bi[i];
    }
    __syncthreads();
    if (tid < 128) {
        float best = rd[tid];
        int   bidx = ri[tid];
        // explicit first-index tiebreak
        for (int t = 1; t < 16; t++) {
            float v  = rd[t * 128 + tid];
            int   vi = ri[t * 128 + tid];
            if (v < best || (v == best && vi < bidx)) { best = v; bidx = vi; }
        }
        sidx[tid] = bidx;
        atomicAdd(&g_counts[bidx], 1.0f);      // integer-valued: deterministic
    }
    __syncthreads();

    // fused gather + quantized output + loss partial (xs still valid).
    // thread t: pixel p = t&127 (coalesced), channels (t>>7)*32 + ii.
    // outq = out+1 is 4-mod-16 aligned -> scalar stores (required).
    {
        const int p   = tid & 127;
        const int c0  = (tid >> 7) * 32;
        const int idx = sidx[p];
        const float* crow = cb + (size_t)idx * DD;
        float* obase = outq + (size_t)b * CC * HWSZ + hw0 + p;
        float part = 0.f;
        #pragma unroll
        for (int ii = 0; ii < 32; ii++) {
            int c = c0 + ii;
            float x  = xs[c * 128 + p];
            float q  = __ldg(&crow[c]);
            float dv = q - x;
            obase[(size_t)c * HWSZ] = x + dv;
            part = __fmaf_rn(dv, dv, part);
        }
        #pragma unroll
        for (int o = 16; o; o >>= 1)
            part += __shfl_xor_sync(0xffffffffu, part, o);
        __shared__ float ws[8];
        if ((tid & 31) == 0) ws[tid >> 5] = part;
        __syncthreads();
        if (tid == 0) {
            float s = 0.f;
            #pragma unroll
            for (int w = 0; w < 8; w++) s += ws[w];
            g_part[blockIdx.x] = s;
        }
    }

    // ---- last-block finalize (threadfence reduction pattern) ----
    __shared__ int is_last;
    if (tid == 0) {
        __threadfence();
        int v = atomicAdd(&g_done, 1);
        is_last = (v == NTILE - 1) ? 1 : 0;
    }
    __syncthreads();
    if (is_last) {
        __threadfence();   // all blocks' g_part/g_counts visible

        float ls = g_part[tid * 2] + g_part[tid * 2 + 1];

        float ent = 0.f;
        #pragma unroll
        for (int i = 0; i < 4; i++) {
            float em = g_counts[tid * 4 + i] * (1.0f / (float)NPIX);
            ent += em * logf(em + 1e-10f);
        }

        #pragma unroll
        for (int o = 16; o; o >>= 1) {
            ls  += __shfl_xor_sync(0xffffffffu, ls, o);
            ent += __shfl_xor_sync(0xffffffffu, ent, o);
        }
        __shared__ float wl[8], we[8];
        if ((tid & 31) == 0) { wl[tid >> 5] = ls; we[tid >> 5] = ent; }
        __syncthreads();
        if (tid == 0) {
            float tl = 0.f, te = 0.f;
            #pragma unroll
            for (int w = 0; w < 8; w++) { tl += wl[w]; te += we[w]; }
            float mean = tl / (float)NEL;
            *loss_out = (1.0f + *beta) * 10.0f * mean;   // KLD_SCALE = 10
            *pp_out   = expf(-te);
        }
    }
}

// ---------------------------------------------------------------------------
// Launch
// ---------------------------------------------------------------------------
extern "C" void kernel_launch(void* const* d_in, const int* in_sizes, int n_in,
                              void* d_out, int out_size) {
    const float* in   = nullptr;
    const float* cb   = nullptr;
    const float* beta = nullptr;
    for (int i = 0; i < n_in; i++) {
        if      (in_sizes[i] == NEL)     in   = (const float*)d_in[i];
        else if (in_sizes[i] == KK * DD) cb   = (const float*)d_in[i];
        else if (in_sizes[i] == 1)       beta = (const float*)d_in[i];
    }

    float* out      = (float*)d_out;
    float* loss_out = out;
    float* q_out    = out + 1;
    float* pp_out   = out + (out_size - 1);

    const int prep_smem = 64 * 65 * 4;           // 16640 B
    const int main_smem = 26368 * 4;             // 105472 B (2 blocks/SM)
    cudaFuncSetAttribute(argmin_fused_kernel,
                         cudaFuncAttributeMaxDynamicSharedMemorySize, main_smem);

    prep_kernel<<<16, 256, prep_smem>>>(cb);
    argmin_fused_kernel<<<NTILE, 256, main_smem>>>(in, cb, q_out,
                                                   beta, loss_out, pp_out);
}

// round 16
// speedup vs baseline: 1.1373x; 1.0008x over previous
#include <cuda_runtime.h>
#include <math.h>
#include <stdint.h>

// Problem constants
#define BB    16
#define CC    64
#define HWSZ  4096
#define NPIX  65536
#define KK    1024
#define DD    64
#define NEL   4194304
#define TILE_P 128
#define CHUNK  128
#define NTILE  512             // NPIX / TILE_P

// Device scratch
__device__ float g_counts[KK];
__device__ float g_cnorm[KK];
__device__ float g_part[NTILE];
__device__ __align__(16) float g_ct[DD * KK];   // transposed codebook [d][k]
__device__ int   g_done;

// ---------------------------------------------------------------------------
// Kernel 1: cnorm (reference rounding) + transposed codebook + zero hist.
// 16 blocks x 256 threads, 64 codes per block; smem-staged for coalescing.
// ---------------------------------------------------------------------------
extern __shared__ float psm[];

__global__ void prep_kernel(const float* __restrict__ cb) {
    const int tid  = threadIdx.x;
    const int base = blockIdx.x * 64;            // 64 codes per block

    // coalesced load: psm[k][65] rows
    for (int i = tid; i < 64 * DD; i += 256) {
        int k = i >> 6, d = i & 63;
        psm[k * 65 + d] = cb[(size_t)(base + k) * DD + d];
    }
    __syncthreads();

    if (tid < 64) {
        float s = 0.f;
        #pragma unroll
        for (int d = 0; d < DD; d++) {
            float v = psm[tid * 65 + d];
            s = __fadd_rn(s, __fmul_rn(v, v));   // reference-exact cn
        }
        g_cnorm[base + tid]  = s;
        g_counts[base + tid] = 0.f;
    }
    // transposed writes: consecutive tid -> consecutive k (coalesced 256B);
    // smem reads stride-65 -> conflict-free
    for (int i = tid; i < 64 * DD; i += 256) {
        int d = i >> 6, k = i & 63;
        g_ct[d * KK + base + k] = psm[k * 65 + d];
    }
    if (blockIdx.x == 0 && tid == 0) g_done = 0;
}

// ---------------------------------------------------------------------------
// cp.async 16B copy of one 128-code chunk (transposed source is contiguous)
// dst rows padded to 132 floats (528B, 16B-aligned).
// ---------------------------------------------------------------------------
__device__ __forceinline__ void issue_chunk_copy(uint32_t cs_addr,
                                                 const float* __restrict__ gsrc,
                                                 int tid) {
    #pragma unroll
    for (int r = 0; r < 8; r++) {
        int i  = tid + r * 256;          // < 2048
        int d  = i >> 5, k4 = i & 31;
        uint32_t dst = cs_addr + (uint32_t)(d * 528 + k4 * 16);
        const float* src = gsrc + d * KK + k4 * 4;
        asm volatile("cp.async.cg.shared.global [%0], [%1], 16;"
                     :: "r"(dst), "l"(src));
    }
}

// ---------------------------------------------------------------------------
// Kernel 2: fused exact argmin (fp32 FFMA GEMM, double-buffered cp.async) +
//           gather + quantized store + loss partial + last-block finalize.
// 512 blocks x 256 threads; block = 128 pixels; thread (tx,ty) owns
// pixels tx*8..+7 and codes ty*8..+7 within each 128-code chunk.
// smem (floats): xs[8192] | cs0[8448] | cs1[8448] | cns[1024] | nss[128] | sidx[128]
// ---------------------------------------------------------------------------
extern __shared__ float smem[];

__global__ void __launch_bounds__(256, 2)
argmin_fused_kernel(const float* __restrict__ in, const float* __restrict__ cb,
                    float* __restrict__ outq,
                    const float* __restrict__ beta,
                    float* __restrict__ loss_out, float* __restrict__ pp_out) {
    float* xs   = smem;                        // 8192
    float* cs0  = smem + 8192;                 // 8448 (64 x 132)
    float* cs1  = smem + 16640;                // 8448
    float* cns  = smem + 25088;                // 1024
    float* nss  = smem + 26112;                // 128
    int*   sidx = (int*)(smem + 26240);        // 128  (total 26368 = 105472B)

    const int tid = threadIdx.x;
    const int tx  = tid & 15;   // pixel group: pixels tx*8 .. +7
    const int ty  = tid >> 4;   // code group:  codes  ty*8 .. +7 (in chunk)

    const uint32_t cs0_a = (uint32_t)__cvta_generic_to_shared(cs0);
    const uint32_t cs1_a = (uint32_t)__cvta_generic_to_shared(cs1);

    const int n0  = blockIdx.x * TILE_P;       // never crosses batch boundary
    const int b   = n0 >> 12;
    const int hw0 = n0 & 4095;
    const float* xin = in + (size_t)b * CC * HWSZ + hw0;

    // prologue: kick off chunk 0 copy before anything else
    issue_chunk_copy(cs0_a, g_ct, tid);
    asm volatile("cp.async.commit_group;" ::: "memory");

    // load x tile: xs[d][p] (coalesced) + all cnorms
    for (int i = tid; i < 64 * 128; i += 256) {
        int d = i >> 7, p = i & 127;
        xs[d * 128 + p] = xin[(size_t)d * HWSZ + p];
    }
    for (int i = tid; i < KK; i += 256) cns[i] = g_cnorm[i];
    __syncthreads();

    // exact ||x||^2 (reference rounding)
    if (tid < 128) {
        float s = 0.f;
        #pragma unroll
        for (int d = 0; d < DD; d++) {
            float v = xs[d * 128 + tid];
            s = __fadd_rn(s, __fmul_rn(v, v));
        }
        nss[tid] = s;
    }

    float bd[8];
    int   bi[8];
    #pragma unroll
    for (int i = 0; i < 8; i++) { bd[i] = 3.4e38f; bi[i] = 0; }

    #pragma unroll 1
    for (int ch = 0; ch < 8; ch++) {
        // issue next chunk copy into the other buffer (safe: that buffer was
        // last read in iteration ch-1, protected by trailing __syncthreads)
        if (ch < 7) {
            issue_chunk_copy((ch & 1) ? cs0_a : cs1_a,
                             g_ct + (ch + 1) * CHUNK, tid);
            asm volatile("cp.async.commit_group;" ::: "memory");
            asm volatile("cp.async.wait_group 1;" ::: "memory");
        } else {
            asm volatile("cp.async.wait_group 0;" ::: "memory");
        }
        __syncthreads();

        const float* cs  = (ch & 1) ? cs1 : cs0;
        const float* cnc = cns + ch * CHUNK;

        float acc[8][8];
        #pragma unroll
        for (int i = 0; i < 8; i++)
            #pragma unroll
            for (int j = 0; j < 8; j++) acc[i][j] = 0.f;

        // dot: strictly d-ascending single-accumulator fp32 FMA chains
        #pragma unroll 2
        for (int d = 0; d < 64; d++) {
            const float4 xa  = *reinterpret_cast<const float4*>(&xs[d * 128 + tx * 8]);
            const float4 xb2 = *reinterpret_cast<const float4*>(&xs[d * 128 + tx * 8 + 4]);
            const float4 ca  = *reinterpret_cast<const float4*>(&cs[d * 132 + ty * 8]);
            const float4 cb2 = *reinterpret_cast<const float4*>(&cs[d * 132 + ty * 8 + 4]);
            float xv[8] = {xa.x, xa.y, xa.z, xa.w, xb2.x, xb2.y, xb2.z, xb2.w};
            float cv[8] = {ca.x, ca.y, ca.z, ca.w, cb2.x, cb2.y, cb2.z, cb2.w};
            #pragma unroll
            for (int i = 0; i < 8; i++)
                #pragma unroll
                for (int j = 0; j < 8; j++)
                    acc[i][j] = __fmaf_rn(xv[i], cv[j], acc[i][j]);
        }

        // score fl(fl(ns+cn) - fl(2*dot)) == fmaf(-2,dot,fl(ns+cn)) (2*dot exact)
        // ascending k + strict '<' keeps first-index min within this thread.
        const int kc = ch * CHUNK;
        #pragma unroll
        for (int i = 0; i < 8; i++) {
            float ns = nss[tx * 8 + i];
            #pragma unroll
            for (int j = 0; j < 8; j++) {
                float s = __fmaf_rn(-2.0f, acc[i][j], __fadd_rn(ns, cnc[ty * 8 + j]));
                if (s < bd[i]) { bd[i] = s; bi[i] = kc + ty * 8 + j; }
            }
        }
        __syncthreads();   // all reads of cs done before its refill (ch+2 issue)
    }

    // cross-thread (over ty) min reduction in cs0 region (xs preserved!)
    // two-phase: 256 threads fold 16 ty-groups -> 2, then 128 combine.
    float* rd = cs0;                           // [16][128]
    int*   ri = (int*)(cs0 + 2048);            // [16][128]
    #pragma unroll
    for (int i = 0; i < 8; i++) {
        rd[ty * 128 + tx * 8 + i] = bd[i];
        ri[ty * 128 + tx * 8 + i] = bi[i];
    }
    __syncthreads();
    {
        // phase 1: thread t handles pixel p = t&127, ty-half h = t>>7 (8 groups)
        const int p = tid & 127;
        const int h = tid >> 7;                // 0 or 1
        float best = rd[(h * 8) * 128 + p];
        int   bidx = ri[(h * 8) * 128 + p];
        #pragma unroll
        for (int t = 1; t < 8; t++) {
            float v  = rd[(h * 8 + t) * 128 + p];
            int   vi = ri[(h * 8 + t) * 128 + p];
            if (v < best || (v == best && vi < bidx)) { best = v; bidx = vi; }
        }
        __syncthreads();
        rd[h * 128 + p] = best;
        ri[h * 128 + p] = bidx;
    }
    __syncthreads();
    if (tid < 128) {
        float best = rd[tid];
        int   bidx = ri[tid];
        float v  = rd[128 + tid];
        int   vi = ri[128 + tid];
        // explicit first-index tiebreak (combine order irrelevant)
        if (v < best || (v == best && vi < bidx)) { best = v; bidx = vi; }
        sidx[tid] = bidx;
        atomicAdd(&g_counts[bidx], 1.0f);      // integer-valued: deterministic
    }
    __syncthreads();

    // fused gather + quantized output + loss partial (xs still valid).
    // thread t: pixel p = t&127 (coalesced), channels (t>>7)*32 + ii.
    // outq = out+1 is 4-mod-16 aligned -> scalar stores (required).
    {
        const int p   = tid & 127;
        const int c0  = (tid >> 7) * 32;
        const int idx = sidx[p];
        const float* crow = cb + (size_t)idx * DD;
        float* obase = outq + (size_t)b * CC * HWSZ + hw0 + p;
        float part = 0.f;
        #pragma unroll
        for (int ii = 0; ii < 32; ii++) {
            int c = c0 + ii;
            float x  = xs[c * 128 + p];
            float q  = __ldg(&crow[c]);
            float dv = q - x;
            obase[(size_t)c * HWSZ] = x + dv;
            part = __fmaf_rn(dv, dv, part);
        }
        #pragma unroll
        for (int o = 16; o; o >>= 1)
            part += __shfl_xor_sync(0xffffffffu, part, o);
        __shared__ float ws[8];
        if ((tid & 31) == 0) ws[tid >> 5] = part;
        __syncthreads();
        if (tid == 0) {
            float s = 0.f;
            #pragma unroll
            for (int w = 0; w < 8; w++) s += ws[w];
            g_part[blockIdx.x] = s;
        }
    }

    // ---- last-block finalize (threadfence reduction pattern) ----
    __shared__ int is_last;
    if (tid == 0) {
        __threadfence();
        int v = atomicAdd(&g_done, 1);
        is_last = (v == NTILE - 1) ? 1 : 0;
    }
    __syncthreads();
    if (is_last) {
        __threadfence();   // all blocks' g_part/g_counts visible

        float ls = g_part[tid * 2] + g_part[tid * 2 + 1];

        float ent = 0.f;
        #pragma unroll
        for (int i = 0; i < 4; i++) {
            float em = g_counts[tid * 4 + i] * (1.0f / (float)NPIX);
            ent += em * logf(em + 1e-10f);
        }

        #pragma unroll
        for (int o = 16; o; o >>= 1) {
            ls  += __shfl_xor_sync(0xffffffffu, ls, o);
            ent += __shfl_xor_sync(0xffffffffu, ent, o);
        }
        __shared__ float wl[8], we[8];
        if ((tid & 31) == 0) { wl[tid >> 5] = ls; we[tid >> 5] = ent; }
        __syncthreads();
        if (tid == 0) {
            float tl = 0.f, te = 0.f;
            #pragma unroll
            for (int w = 0; w < 8; w++) { tl += wl[w]; te += we[w]; }
            float mean = tl / (float)NEL;
            *loss_out = (1.0f + *beta) * 10.0f * mean;   // KLD_SCALE = 10
            *pp_out   = expf(-te);
        }
    }
}

// ---------------------------------------------------------------------------
// Launch
// ---------------------------------------------------------------------------
extern "C" void kernel_launch(void* const* d_in, const int* in_sizes, int n_in,
                              void* d_out, int out_size) {
    const float* in   = nullptr;
    const float* cb   = nullptr;
    const float* beta = nullptr;
    for (int i = 0; i < n_in; i++) {
        if      (in_sizes[i] == NEL)     in   = (const float*)d_in[i];
        else if (in_sizes[i] == KK * DD) cb   = (const float*)d_in[i];
        else if (in_sizes[i] == 1)       beta = (const float*)d_in[i];
    }

    float* out      = (float*)d_out;
    float* loss_out = out;
    float* q_out    = out + 1;
    float* pp_out   = out + (out_size - 1);

    const int prep_smem = 64 * 65 * 4;           // 16640 B
    const int main_smem = 26368 * 4;             // 105472 B (2 blocks/SM)
    cudaFuncSetAttribute(argmin_fused_kernel,
                         cudaFuncAttributeMaxDynamicSharedMemorySize, main_smem);

    prep_kernel<<<16, 256, prep_smem>>>(cb);
    argmin_fused_kernel<<<NTILE, 256, main_smem>>>(in, cb, q_out,
                                                   beta, loss_out, pp_out);
}